// round 1
// baseline (speedup 1.0000x reference)
#include <cuda_runtime.h>
#include <math.h>

// ============================================================================
// InterEdgeAtten collapses algebraically:
//   attn = softmax(sim, -1); out_core = v * attn.sum(-1) = v   (softmax rows sum to 1)
// so q/k/bias/masks are dead. Remaining computation:
//   out = ( sigmoid(X @ Wg_perm + bg_perm) * (X @ Wv) ) @ Wo + bo
// where Wg_perm[:, m] = Wg[:, (m%64)*4 + m/64]  (gate uses (d h) split, v uses (h d)).
// X: [65536,128] fp32, INNER=256, out: [65536,128] fp32.
// ============================================================================

#define TM        64
#define NTHREADS  256
#define E_DIM     128
#define INNER_DIM 256

// permuted gate weights scratch (static device globals: allocation-free)
__device__ float g_WgP[E_DIM * INNER_DIM];
__device__ float g_bgP[INNER_DIM];

__global__ void permute_wg_kernel(const float* __restrict__ Wg,
                                  const float* __restrict__ bg) {
    int idx = blockIdx.x * blockDim.x + threadIdx.x;   // 32768 threads
    if (idx < E_DIM * INNER_DIM) {
        int m = idx & (INNER_DIM - 1);
        int k = idx >> 8;
        int src = ((m & 63) << 2) | (m >> 6);          // (m%64)*4 + m/64
        g_WgP[k * INNER_DIM + m] = Wg[k * INNER_DIM + src];
        if (k == 0) g_bgP[m] = bg[src];
    }
}

// Fused gated-MLP kernel.
// Grid: rows/64 CTAs, 256 threads (16x16 thread grid: ty=row group, tx=col group).
// smem: Xs[64][132] | Wvs[128][64] + Wgs[128][64] (reused as Wos[64][132]) | Tb[64][68]
__global__ __launch_bounds__(NTHREADS, 1)
void fused_gated_mlp(const float* __restrict__ X,
                     const float* __restrict__ Wv,
                     const float* __restrict__ Wo,
                     const float* __restrict__ bo,
                     float* __restrict__ out) {
    extern __shared__ float sm[];
    float* Xs  = sm;                       // 64*132  = 8448 floats
    float* Wvs = sm + 64 * 132;            // 128*64  = 8192
    float* Wgs = Wvs + 128 * 64;           // 128*64  = 8192
    float* Wos = Wvs;                      // 64*132  = 8448 (aliases Wvs+Wgs region)
    float* Tb  = Wgs + 128 * 64;           // 64*68   = 4352
                                           // total 29184 floats = 116736 B

    const int tid = threadIdx.x;
    const int tx  = tid & 15;
    const int ty  = tid >> 4;
    const int r0  = blockIdx.x * TM;

    // ---- load X tile [64][128] -> Xs [64][132] (padded: conflict-free k-broadcast reads)
    #pragma unroll
    for (int it = tid; it < TM * 32; it += NTHREADS) {
        int row = it >> 5, kq = (it & 31) * 4;
        float4 v = *reinterpret_cast<const float4*>(X + (size_t)(r0 + row) * 128 + kq);
        *reinterpret_cast<float4*>(Xs + row * 132 + kq) = v;
    }

    float o[4][8];
    #pragma unroll
    for (int r = 0; r < 4; ++r)
        #pragma unroll
        for (int c = 0; c < 8; ++c) o[r][c] = 0.f;

    for (int nt = 0; nt < 4; ++nt) {
        const int n0 = nt * 64;

        // ---- load Wv / Wg_perm 64-col tiles: [128][64]
        #pragma unroll
        for (int it = tid; it < 128 * 16; it += NTHREADS) {
            int row = it >> 4, c4 = (it & 15) * 4;
            *reinterpret_cast<float4*>(Wvs + row * 64 + c4) =
                *reinterpret_cast<const float4*>(Wv + row * 256 + n0 + c4);
            *reinterpret_cast<float4*>(Wgs + row * 64 + c4) =
                *reinterpret_cast<const float4*>(g_WgP + row * 256 + n0 + c4);
        }
        float bgp[4];
        #pragma unroll
        for (int c = 0; c < 4; ++c) bgp[c] = g_bgP[n0 + tx * 4 + c];
        __syncthreads();

        // ---- GEMM1: accV = Xs @ Wvs, accG = Xs @ Wgs   (each thread: 4x4 + 4x4)
        float accV[4][4], accG[4][4];
        #pragma unroll
        for (int r = 0; r < 4; ++r)
            #pragma unroll
            for (int c = 0; c < 4; ++c) { accV[r][c] = 0.f; accG[r][c] = 0.f; }

        #pragma unroll 8
        for (int k = 0; k < 128; ++k) {
            float a[4];
            #pragma unroll
            for (int r = 0; r < 4; ++r) a[r] = Xs[(ty * 4 + r) * 132 + k];
            float4 bv = *reinterpret_cast<const float4*>(Wvs + k * 64 + tx * 4);
            float4 bg4 = *reinterpret_cast<const float4*>(Wgs + k * 64 + tx * 4);
            #pragma unroll
            for (int r = 0; r < 4; ++r) {
                accV[r][0] += a[r] * bv.x;  accG[r][0] += a[r] * bg4.x;
                accV[r][1] += a[r] * bv.y;  accG[r][1] += a[r] * bg4.y;
                accV[r][2] += a[r] * bv.z;  accG[r][2] += a[r] * bg4.z;
                accV[r][3] += a[r] * bv.w;  accG[r][3] += a[r] * bg4.w;
            }
        }

        // ---- gate + stage T block [64][64] -> Tb (padded stride 68)
        #pragma unroll
        for (int r = 0; r < 4; ++r)
            #pragma unroll
            for (int c = 0; c < 4; ++c) {
                float g = 1.f / (1.f + __expf(-(accG[r][c] + bgp[c])));
                Tb[(ty * 4 + r) * 68 + tx * 4 + c] = g * accV[r][c];
            }
        __syncthreads();   // Wvs/Wgs reads done + Tb visible

        // ---- load Wo strip rows [n0, n0+64) -> Wos [64][132]  (aliases Wvs/Wgs)
        #pragma unroll
        for (int it = tid; it < 64 * 32; it += NTHREADS) {
            int row = it >> 5, q = (it & 31) * 4;
            *reinterpret_cast<float4*>(Wos + row * 132 + q) =
                *reinterpret_cast<const float4*>(Wo + (size_t)(n0 + row) * 128 + q);
        }
        __syncthreads();

        // ---- GEMM2 partial: o += Tb[64x64] @ Wos[64x128]   (each thread: 4x8)
        #pragma unroll 8
        for (int kk = 0; kk < 64; ++kk) {
            float a2[4];
            #pragma unroll
            for (int r = 0; r < 4; ++r) a2[r] = Tb[(ty * 4 + r) * 68 + kk];
            float4 b0 = *reinterpret_cast<const float4*>(Wos + kk * 132 + tx * 8);
            float4 b1 = *reinterpret_cast<const float4*>(Wos + kk * 132 + tx * 8 + 4);
            #pragma unroll
            for (int r = 0; r < 4; ++r) {
                o[r][0] += a2[r] * b0.x;  o[r][1] += a2[r] * b0.y;
                o[r][2] += a2[r] * b0.z;  o[r][3] += a2[r] * b0.w;
                o[r][4] += a2[r] * b1.x;  o[r][5] += a2[r] * b1.y;
                o[r][6] += a2[r] * b1.z;  o[r][7] += a2[r] * b1.w;
            }
        }
        __syncthreads();   // Tb/Wos reads done before next tile overwrites
    }

    // ---- epilogue: + bo, store
    float bov[8];
    #pragma unroll
    for (int c = 0; c < 8; ++c) bov[c] = bo[tx * 8 + c];
    #pragma unroll
    for (int r = 0; r < 4; ++r) {
        size_t row = (size_t)(r0 + ty * 4 + r);
        float4 v0, v1;
        v0.x = o[r][0] + bov[0]; v0.y = o[r][1] + bov[1];
        v0.z = o[r][2] + bov[2]; v0.w = o[r][3] + bov[3];
        v1.x = o[r][4] + bov[4]; v1.y = o[r][5] + bov[5];
        v1.z = o[r][6] + bov[6]; v1.w = o[r][7] + bov[7];
        *reinterpret_cast<float4*>(out + row * 128 + tx * 8)     = v0;
        *reinterpret_cast<float4*>(out + row * 128 + tx * 8 + 4) = v1;
    }
}

extern "C" void kernel_launch(void* const* d_in, const int* in_sizes, int n_in,
                              void* d_out, int out_size) {
    // metadata order: inter_edges, ab_mask, at_mask, Wq, Wk, Wv, Web, Wg, bg, Wo, bo
    const float* X  = (const float*)d_in[0];
    const float* Wv = (const float*)d_in[5];
    const float* Wg = (const float*)d_in[7];
    const float* bg = (const float*)d_in[8];
    const float* Wo = (const float*)d_in[9];
    const float* bo = (const float*)d_in[10];
    float* out = (float*)d_out;

    const int rows = in_sizes[0] / E_DIM;          // 65536
    const int grid = rows / TM;                    // 1024

    permute_wg_kernel<<<(E_DIM * INNER_DIM + 255) / 256, 256>>>(Wg, bg);

    const size_t smem_bytes = (size_t)(64 * 132 + 2 * 128 * 64 + 64 * 68) * sizeof(float);
    cudaFuncSetAttribute(fused_gated_mlp,
                         cudaFuncAttributeMaxDynamicSharedMemorySize,
                         (int)smem_bytes);
    fused_gated_mlp<<<grid, NTHREADS, smem_bytes>>>(X, Wv, Wo, bo, out);
}

// round 2
// speedup vs baseline: 1.0042x; 1.0042x over previous
#include <cuda_runtime.h>
#include <math.h>

// ============================================================================
// InterEdgeAtten collapses algebraically:
//   attn = softmax(sim, -1); out_core = v * attn.sum(-1) = v   (softmax rows sum to 1)
// so q/k/bias/masks are dead. Remaining computation:
//   out = ( sigmoid(X @ Wg_perm + bg_perm) * (X @ Wv) ) @ Wo + bo
// where Wg_perm[:, m] = Wg[:, (m%64)*4 + m/64]  (gate uses (d h) split, v uses (h d)).
// X: [65536,128] fp32, INNER=256, out: [65536,128] fp32.
// ============================================================================

#define TM        64
#define NTHREADS  256
#define E_DIM     128
#define INNER_DIM 256

// permuted gate weights scratch (static device globals: allocation-free)
__device__ float g_WgP[E_DIM * INNER_DIM];
__device__ float g_bgP[INNER_DIM];

__global__ void permute_wg_kernel(const float* __restrict__ Wg,
                                  const float* __restrict__ bg) {
    int idx = blockIdx.x * blockDim.x + threadIdx.x;   // 32768 threads
    if (idx < E_DIM * INNER_DIM) {
        int m = idx & (INNER_DIM - 1);
        int k = idx >> 8;
        int src = ((m & 63) << 2) | (m >> 6);          // (m%64)*4 + m/64
        g_WgP[k * INNER_DIM + m] = Wg[k * INNER_DIM + src];
        if (k == 0) g_bgP[m] = bg[src];
    }
}

// Fused gated-MLP kernel.
// Grid: rows/64 CTAs, 256 threads (16x16 thread grid: ty=row group, tx=col group).
// smem: Xs[64][132] | Wvs[128][64] + Wgs[128][64] (reused as Wos[64][132]) | Tb[64][68]
__global__ __launch_bounds__(NTHREADS, 1)
void fused_gated_mlp(const float* __restrict__ X,
                     const float* __restrict__ Wv,
                     const float* __restrict__ Wo,
                     const float* __restrict__ bo,
                     float* __restrict__ out) {
    extern __shared__ float sm[];
    float* Xs  = sm;                       // 64*132  = 8448 floats
    float* Wvs = sm + 64 * 132;            // 128*64  = 8192
    float* Wgs = Wvs + 128 * 64;           // 128*64  = 8192
    float* Wos = Wvs;                      // 64*132  = 8448 (aliases Wvs+Wgs region)
    float* Tb  = Wgs + 128 * 64;           // 64*68   = 4352
                                           // total 29184 floats = 116736 B

    const int tid = threadIdx.x;
    const int tx  = tid & 15;
    const int ty  = tid >> 4;
    const int r0  = blockIdx.x * TM;

    // ---- load X tile [64][128] -> Xs [64][132] (padded: conflict-free k-broadcast reads)
    #pragma unroll
    for (int it = tid; it < TM * 32; it += NTHREADS) {
        int row = it >> 5, kq = (it & 31) * 4;
        float4 v = *reinterpret_cast<const float4*>(X + (size_t)(r0 + row) * 128 + kq);
        *reinterpret_cast<float4*>(Xs + row * 132 + kq) = v;
    }

    float o[4][8];
    #pragma unroll
    for (int r = 0; r < 4; ++r)
        #pragma unroll
        for (int c = 0; c < 8; ++c) o[r][c] = 0.f;

    for (int nt = 0; nt < 4; ++nt) {
        const int n0 = nt * 64;

        // ---- load Wv / Wg_perm 64-col tiles: [128][64]
        #pragma unroll
        for (int it = tid; it < 128 * 16; it += NTHREADS) {
            int row = it >> 4, c4 = (it & 15) * 4;
            *reinterpret_cast<float4*>(Wvs + row * 64 + c4) =
                *reinterpret_cast<const float4*>(Wv + row * 256 + n0 + c4);
            *reinterpret_cast<float4*>(Wgs + row * 64 + c4) =
                *reinterpret_cast<const float4*>(g_WgP + row * 256 + n0 + c4);
        }
        float bgp[4];
        #pragma unroll
        for (int c = 0; c < 4; ++c) bgp[c] = g_bgP[n0 + tx * 4 + c];
        __syncthreads();

        // ---- GEMM1: accV = Xs @ Wvs, accG = Xs @ Wgs   (each thread: 4x4 + 4x4)
        float accV[4][4], accG[4][4];
        #pragma unroll
        for (int r = 0; r < 4; ++r)
            #pragma unroll
            for (int c = 0; c < 4; ++c) { accV[r][c] = 0.f; accG[r][c] = 0.f; }

        #pragma unroll 8
        for (int k = 0; k < 128; ++k) {
            float a[4];
            #pragma unroll
            for (int r = 0; r < 4; ++r) a[r] = Xs[(ty * 4 + r) * 132 + k];
            float4 bv = *reinterpret_cast<const float4*>(Wvs + k * 64 + tx * 4);
            float4 bg4 = *reinterpret_cast<const float4*>(Wgs + k * 64 + tx * 4);
            #pragma unroll
            for (int r = 0; r < 4; ++r) {
                accV[r][0] += a[r] * bv.x;  accG[r][0] += a[r] * bg4.x;
                accV[r][1] += a[r] * bv.y;  accG[r][1] += a[r] * bg4.y;
                accV[r][2] += a[r] * bv.z;  accG[r][2] += a[r] * bg4.z;
                accV[r][3] += a[r] * bv.w;  accG[r][3] += a[r] * bg4.w;
            }
        }

        // ---- gate + stage T block [64][64] -> Tb (padded stride 68)
        #pragma unroll
        for (int r = 0; r < 4; ++r)
            #pragma unroll
            for (int c = 0; c < 4; ++c) {
                float g = 1.f / (1.f + __expf(-(accG[r][c] + bgp[c])));
                Tb[(ty * 4 + r) * 68 + tx * 4 + c] = g * accV[r][c];
            }
        __syncthreads();   // Wvs/Wgs reads done + Tb visible

        // ---- load Wo strip rows [n0, n0+64) -> Wos [64][132]  (aliases Wvs/Wgs)
        #pragma unroll
        for (int it = tid; it < 64 * 32; it += NTHREADS) {
            int row = it >> 5, q = (it & 31) * 4;
            *reinterpret_cast<float4*>(Wos + row * 132 + q) =
                *reinterpret_cast<const float4*>(Wo + (size_t)(n0 + row) * 128 + q);
        }
        __syncthreads();

        // ---- GEMM2 partial: o += Tb[64x64] @ Wos[64x128]   (each thread: 4x8)
        #pragma unroll 8
        for (int kk = 0; kk < 64; ++kk) {
            float a2[4];
            #pragma unroll
            for (int r = 0; r < 4; ++r) a2[r] = Tb[(ty * 4 + r) * 68 + kk];
            float4 b0 = *reinterpret_cast<const float4*>(Wos + kk * 132 + tx * 8);
            float4 b1 = *reinterpret_cast<const float4*>(Wos + kk * 132 + tx * 8 + 4);
            #pragma unroll
            for (int r = 0; r < 4; ++r) {
                o[r][0] += a2[r] * b0.x;  o[r][1] += a2[r] * b0.y;
                o[r][2] += a2[r] * b0.z;  o[r][3] += a2[r] * b0.w;
                o[r][4] += a2[r] * b1.x;  o[r][5] += a2[r] * b1.y;
                o[r][6] += a2[r] * b1.z;  o[r][7] += a2[r] * b1.w;
            }
        }
        __syncthreads();   // Tb/Wos reads done before next tile overwrites
    }

    // ---- epilogue: + bo, store
    float bov[8];
    #pragma unroll
    for (int c = 0; c < 8; ++c) bov[c] = bo[tx * 8 + c];
    #pragma unroll
    for (int r = 0; r < 4; ++r) {
        size_t row = (size_t)(r0 + ty * 4 + r);
        float4 v0, v1;
        v0.x = o[r][0] + bov[0]; v0.y = o[r][1] + bov[1];
        v0.z = o[r][2] + bov[2]; v0.w = o[r][3] + bov[3];
        v1.x = o[r][4] + bov[4]; v1.y = o[r][5] + bov[5];
        v1.z = o[r][6] + bov[6]; v1.w = o[r][7] + bov[7];
        *reinterpret_cast<float4*>(out + row * 128 + tx * 8)     = v0;
        *reinterpret_cast<float4*>(out + row * 128 + tx * 8 + 4) = v1;
    }
}

extern "C" void kernel_launch(void* const* d_in, const int* in_sizes, int n_in,
                              void* d_out, int out_size) {
    // metadata order: inter_edges, ab_mask, at_mask, Wq, Wk, Wv, Web, Wg, bg, Wo, bo
    const float* X  = (const float*)d_in[0];
    const float* Wv = (const float*)d_in[5];
    const float* Wg = (const float*)d_in[7];
    const float* bg = (const float*)d_in[8];
    const float* Wo = (const float*)d_in[9];
    const float* bo = (const float*)d_in[10];
    float* out = (float*)d_out;

    const int rows = in_sizes[0] / E_DIM;          // 65536
    const int grid = rows / TM;                    // 1024

    permute_wg_kernel<<<(E_DIM * INNER_DIM + 255) / 256, 256>>>(Wg, bg);

    const size_t smem_bytes = (size_t)(64 * 132 + 2 * 128 * 64 + 64 * 68) * sizeof(float);
    cudaFuncSetAttribute(fused_gated_mlp,
                         cudaFuncAttributeMaxDynamicSharedMemorySize,
                         (int)smem_bytes);
    fused_gated_mlp<<<grid, NTHREADS, smem_bytes>>>(X, Wv, Wo, bo, out);
}